// round 6
// baseline (speedup 1.0000x reference)
#include <cuda_runtime.h>
#include <cstdint>

// Problem constants: B=1024, FANOUTS=[10,25], DIM=256, N_NODES=100000
#define DIM   256
#define D4    64      // DIM / 4

typedef unsigned long long u64;

// Scratch (device globals; allocation-free per harness rules)
__device__ float g_n1[10240 * DIM];   // layer0 output on hop-1 nodes
__device__ float g_n0[1024  * DIM];   // layer0 output on hop-0 nodes
__device__ float g_Wt0[256 * 256];    // layer0 packed weights
__device__ float g_Wt1[256 * 256];    // layer1 packed weights

__device__ __forceinline__ u64 ffma2(u64 a, u64 b, u64 c) {
    u64 d;
    asm("fma.rn.f32x2 %0, %1, %2, %3;" : "=l"(d) : "l"(a), "l"(b), "l"(c));
    return d;
}

// Pack [Ws|Wn] (each [256,128] row-major, k-major) into blocked transposed
// layout Wt[k/8][c][k%8] (c in [0,256): 0-127 self cols, 128-255 neigh cols).
// A GEMM thread then reads 8 k-values for its column as 32 contiguous bytes.
__global__ void __launch_bounds__(256)
pack_weights(const float* __restrict__ W0s, const float* __restrict__ W0n,
             const float* __restrict__ W1s, const float* __restrict__ W1n)
{
    const int idx = blockIdx.x * 256 + threadIdx.x;   // 0 .. 131071
    const int l = idx >> 16;
    const int k = (idx >> 8) & 255;
    const int c = idx & 255;
    const float* Ws = l ? W1s : W0s;
    const float* Wn = l ? W1n : W0n;
    const float v = (c < 128) ? Ws[k * 128 + c] : Wn[k * 128 + (c - 128)];
    float* dst = l ? g_Wt1 : g_Wt0;
    dst[(k >> 3) * 2048 + c * 8 + (k & 7)] = v;
}

// One fused tile of TM rows:
//   Xs[r] = ssrc[ sidx? sidx[row] : row ]
//   Xn[r] = mean_{j<F} nsrc[ nidx? nidx[row*F+j] : row*F+j ]
//   out[row][c]     = act( Xs[r] . W[:,c]      )   c in [0,128)
//   out[row][128+c] = act( Xn[r] . W[:,128+c] )
template <int TM, int F, int THREADS, bool RELU, bool IDX>
__device__ __forceinline__ void sage_tile(
    const float4* __restrict__ ssrc4,
    const float4* __restrict__ nsrc4,
    const int*    __restrict__ sidx,
    const int*    __restrict__ nidx,
    const float*  __restrict__ Wt,    // packed [32][256][8]
    float*        __restrict__ out,   // [nrows,256]
    int m0,
    float4* Xs4, float4* Xn4)
{
    const int tid = threadIdx.x;
    constexpr int ITEMS = TM * D4;

    // ---- gather + mean: one (row, float4-slot) per thread per step ----
    #pragma unroll
    for (int it = 0; it < ITEMS / THREADS; ++it) {
        const int i = it * THREADS + tid;
        const int r   = i >> 6;
        const int q   = i & 63;
        const int row = m0 + r;

        const int gs = IDX ? __ldg(sidx + row) : row;
        Xs4[i] = __ldcg(ssrc4 + (size_t)gs * D4 + q);   // L2-only: keep L1 for W

        float4 a0 = make_float4(0.f, 0.f, 0.f, 0.f);
        float4 a1 = make_float4(0.f, 0.f, 0.f, 0.f);
        const size_t nb = (size_t)row * F;
        #pragma unroll
        for (int j = 0; j < F; j += 2) {
            const int g0 = IDX ? __ldg(nidx + nb + j) : (int)(nb + j);
            const float4 v0 = __ldcg(nsrc4 + (size_t)g0 * D4 + q);
            a0.x += v0.x; a0.y += v0.y; a0.z += v0.z; a0.w += v0.w;
            if (j + 1 < F) {
                const int g1 = IDX ? __ldg(nidx + nb + j + 1) : (int)(nb + j + 1);
                const float4 v1 = __ldcg(nsrc4 + (size_t)g1 * D4 + q);
                a1.x += v1.x; a1.y += v1.y; a1.z += v1.z; a1.w += v1.w;
            }
        }
        const float inv = 1.0f / (float)F;
        a0.x = (a0.x + a1.x) * inv; a0.y = (a0.y + a1.y) * inv;
        a0.z = (a0.z + a1.z) * inv; a0.w = (a0.w + a1.w) * inv;
        Xn4[i] = a0;
    }
    __syncthreads();

    // ---- GEMM: thread -> (column pair (c2, c2+128), RPT rows) ----
    constexpr int RG  = THREADS / 128;
    constexpr int RPT = TM / RG;
    const int c2 = tid & 127;
    const int r0 = (tid >> 7) * RPT;
    const float* Xs = reinterpret_cast<const float*>(Xs4);
    const float* Xn = reinterpret_cast<const float*>(Xn4);
    const ulonglong2* __restrict__ Wt2 =
        reinterpret_cast<const ulonglong2*>(Wt);

    u64 accA[RPT], accB[RPT];
    #pragma unroll
    for (int r = 0; r < RPT; ++r) { accA[r] = 0ull; accB[r] = 0ull; }

    #pragma unroll 2
    for (int kb = 0; kb < 32; ++kb) {           // 8 k-values per iteration
        const int base = kb * 512;              // ulonglong2 units per kb block
        const ulonglong2 wa0 = __ldg(Wt2 + base + c2 * 2);
        const ulonglong2 wa1 = __ldg(Wt2 + base + c2 * 2 + 1);
        const ulonglong2 wb0 = __ldg(Wt2 + base + (128 + c2) * 2);
        const ulonglong2 wb1 = __ldg(Wt2 + base + (128 + c2) * 2 + 1);
        #pragma unroll
        for (int r = 0; r < RPT; ++r) {
            const float* xsr = Xs + (r0 + r) * DIM + kb * 8;
            const ulonglong2 xs0 = *reinterpret_cast<const ulonglong2*>(xsr);
            const ulonglong2 xs1 = *reinterpret_cast<const ulonglong2*>(xsr + 4);
            accA[r] = ffma2(xs0.x, wa0.x, accA[r]);
            accA[r] = ffma2(xs0.y, wa0.y, accA[r]);
            accA[r] = ffma2(xs1.x, wa1.x, accA[r]);
            accA[r] = ffma2(xs1.y, wa1.y, accA[r]);
            const float* xnr = Xn + (r0 + r) * DIM + kb * 8;
            const ulonglong2 xn0 = *reinterpret_cast<const ulonglong2*>(xnr);
            const ulonglong2 xn1 = *reinterpret_cast<const ulonglong2*>(xnr + 4);
            accB[r] = ffma2(xn0.x, wb0.x, accB[r]);
            accB[r] = ffma2(xn0.y, wb0.y, accB[r]);
            accB[r] = ffma2(xn1.x, wb1.x, accB[r]);
            accB[r] = ffma2(xn1.y, wb1.y, accB[r]);
        }
    }

    #pragma unroll
    for (int r = 0; r < RPT; ++r) {
        float vA = __uint_as_float((unsigned)(accA[r] & 0xffffffffull))
                 + __uint_as_float((unsigned)(accA[r] >> 32));
        float vB = __uint_as_float((unsigned)(accB[r] & 0xffffffffull))
                 + __uint_as_float((unsigned)(accB[r] >> 32));
        if (RELU) { vA = fmaxf(vA, 0.0f); vB = fmaxf(vB, 0.0f); }
        float* o = out + (size_t)(m0 + r0 + r) * DIM;
        o[c2]       = vA;
        o[128 + c2] = vB;
    }
}

// K1: layer 0. blocks [0,320): n1 (10240 rows, F=25); [320,352): n0 (F=10).
// TM=32, 512 threads, 64KB dynamic smem -> 2 CTAs/SM (phase overlap).
extern __shared__ float4 smem_dyn[];

__global__ void __launch_bounds__(512, 2)
sage_layer0_kernel(const float4* __restrict__ feat4,
                   const int* __restrict__ sn0,
                   const int* __restrict__ sn1,
                   const int* __restrict__ sn2,
                   float* __restrict__ n1,
                   float* __restrict__ n0)
{
    float4* Xs4 = smem_dyn;
    float4* Xn4 = smem_dyn + 32 * D4;
    if (blockIdx.x < 320) {
        sage_tile<32, 25, 512, true, true>(
            feat4, feat4, sn1, sn2, g_Wt0, n1, blockIdx.x * 32, Xs4, Xn4);
    } else {
        sage_tile<32, 10, 512, true, true>(
            feat4, feat4, sn0, sn1, g_Wt0, n0, (blockIdx.x - 320) * 32, Xs4, Xn4);
    }
}

// K2: layer 1 (no activation). self = n0 rows, neigh = mean10 of contiguous
// n1 rows. TM=4, 256 threads -> 256 CTAs.
__global__ void __launch_bounds__(256)
sage_layer1_kernel(const float4* __restrict__ n0_4,
                   const float4* __restrict__ n1_4,
                   float* __restrict__ out)
{
    __shared__ float4 Xs4[4 * D4];
    __shared__ float4 Xn4[4 * D4];
    sage_tile<4, 10, 256, false, false>(
        n0_4, n1_4, nullptr, nullptr, g_Wt1, out, blockIdx.x * 4, Xs4, Xn4);
}

// =============================================================================
extern "C" void kernel_launch(void* const* d_in, const int* in_sizes, int n_in,
                              void* d_out, int out_size)
{
    const float4* feat4 = (const float4*)d_in[0];
    const int*    sn0   = (const int*)  d_in[1];
    const int*    sn1   = (const int*)  d_in[2];
    const int*    sn2   = (const int*)  d_in[3];
    const float*  W0s   = (const float*)d_in[4];
    const float*  W0n   = (const float*)d_in[5];
    const float*  W1s   = (const float*)d_in[6];
    const float*  W1n   = (const float*)d_in[7];
    float*        out   = (float*)      d_out;

    float* n1 = nullptr;
    float* n0 = nullptr;
    cudaGetSymbolAddress((void**)&n1, g_n1);
    cudaGetSymbolAddress((void**)&n0, g_n0);

    static bool attr_set = false;
    if (!attr_set) {
        cudaFuncSetAttribute(sage_layer0_kernel,
                             cudaFuncAttributeMaxDynamicSharedMemorySize,
                             64 * 1024);
        attr_set = true;
    }

    pack_weights<<<512, 256>>>(W0s, W0n, W1s, W1n);
    sage_layer0_kernel<<<352, 512, 64 * 1024>>>(feat4, sn0, sn1, sn2, n1, n0);
    sage_layer1_kernel<<<256, 256>>>((const float4*)n0, (const float4*)n1, out);
}